// round 6
// baseline (speedup 1.0000x reference)
#include <cuda_runtime.h>
#include <cstdint>

// ---------------------------------------------------------------------------
// YoloLoss on [N=32768, 6, 8, 14] fp32: persistent TRIPLE-buffered
// cp.async.bulk (TMA bulk) pipeline. 296 persistent CTAs x 256 threads
// (2 CTAs/SM, 86KB smem each). Tile = 256 cells (14336 B per tensor).
// While tile j is being consumed, tiles j+1 and j+2 are in flight, keeping
// ~114KB of DRAM demand outstanding per SM. Thread 0 issues tile j+3 into
// the freed stage right after the consumption barrier.
// Last-finishing block finalizes out[0] and resets scratch state.
// ---------------------------------------------------------------------------

#define CELL_F 14
#define TPB 256
#define TILE_CELLS 256
#define TILE_FLOATS (TILE_CELLS * CELL_F)   // 3584 floats
#define TILE_BYTES  (TILE_FLOATS * 4)       // 14336 bytes
#define STAGES 3
#define GRID_BLOCKS 296                     // 148 SMs x 2 (smem-limited)

#define LAMBDA_COORD 8.0f
#define LAMBDA_CLASS 0.7f
#define EPS_IOU 1e-10f

__device__ double g_yolo_acc;          // zero-init; reset by last block
__device__ unsigned int g_yolo_count;  // zero-init; reset by last block

__device__ __forceinline__ uint32_t smem_u32(const void* p) {
    return (uint32_t)__cvta_generic_to_shared((void*)p);
}

__device__ __forceinline__ void mbar_init(uint32_t mb, uint32_t count) {
    asm volatile("mbarrier.init.shared::cta.b64 [%0], %1;"
                 :: "r"(mb), "r"(count) : "memory");
}

__device__ __forceinline__ void mbar_wait(uint32_t mb, uint32_t phase) {
    uint32_t done = 0;
    while (!done) {
        asm volatile(
            "{\n\t.reg .pred p;\n\t"
            "mbarrier.try_wait.parity.acquire.cta.shared::cta.b64 p, [%1], %2, 0x989680;\n\t"
            "selp.b32 %0, 1, 0, p;\n\t}"
            : "=r"(done) : "r"(mb), "r"(phase) : "memory");
    }
}

__device__ __forceinline__ void issue_tile(const float* __restrict__ pred,
                                           const float* __restrict__ gt,
                                           float* dynsmem, int s,
                                           long long tile, uint32_t mb)
{
    asm volatile("mbarrier.arrive.expect_tx.shared::cta.b64 _, [%0], %1;"
                 :: "r"(mb), "r"(2u * TILE_BYTES) : "memory");
    const char* srcp = (const char*)pred + tile * (long long)TILE_BYTES;
    const char* srcg = (const char*)gt   + tile * (long long)TILE_BYTES;
    uint32_t dso = smem_u32(dynsmem + (size_t)s * 2 * TILE_FLOATS);
    uint32_t dsg = dso + TILE_BYTES;
    asm volatile("cp.async.bulk.shared::cluster.global.mbarrier::complete_tx::bytes "
                 "[%0], [%1], %2, [%3];"
                 :: "r"(dso), "l"(srcp), "r"((uint32_t)TILE_BYTES), "r"(mb) : "memory");
    asm volatile("cp.async.bulk.shared::cluster.global.mbarrier::complete_tx::bytes "
                 "[%0], [%1], %2, [%3];"
                 :: "r"(dsg), "l"(srcg), "r"((uint32_t)TILE_BYTES), "r"(mb) : "memory");
}

__device__ __forceinline__ float cell_loss(const float* __restrict__ o,
                                           const float* __restrict__ g)
{
    const float obj_flag = g[4];  // exactly 0.0f or 1.0f
    if (obj_flag > 0.0f) {
        const float gx = g[0], gy = g[1];
        const float gw = g[2] * g[2], gh = g[3] * g[3];
        const float garea = gw * gh;

        float iou[2];
        #pragma unroll
        for (int b = 0; b < 2; b++) {
            const float x = o[5 * b + 0];
            const float y = o[5 * b + 1];
            const float w = o[5 * b + 2] * o[5 * b + 2];
            const float h = o[5 * b + 3] * o[5 * b + 3];
            const float left  = fmaxf(x - 0.5f * w, gx - 0.5f * gw);
            const float right = fminf(x + 0.5f * w, gx + 0.5f * gw);
            const float top   = fmaxf(y - 0.5f * h, gy - 0.5f * gh);
            const float bot   = fminf(y + 0.5f * h, gy + 0.5f * gh);
            const float inter = fmaxf(right - left, 0.0f) * fmaxf(bot - top, 0.0f);
            const float uni   = w * h + garea - inter;
            iou[b] = inter / (uni + EPS_IOU);
        }
        // jnp.argmax picks FIRST max -> responsible=1 only on strict >
        const int idx = (iou[1] > iou[0]) ? 1 : 0;
        const float max_iou = fmaxf(iou[0], iou[1]);

        const float* pr = o + 5 * idx;
        const float* po = o + 5 * (1 - idx);
        const float* gr = g + 5 * idx;
        const float* go = g + 5 * (1 - idx);

        float loc = 0.0f;
        #pragma unroll
        for (int c = 0; c < 4; c++) {
            const float d = pr[c] - gr[c];
            loc = fmaf(d, d, loc);
        }
        const float dc = pr[4] - max_iou;
        const float dn = po[4] - go[4];

        float cls = 0.0f;
        #pragma unroll
        for (int c = 10; c < 14; c++) {
            const float d = o[c] - g[c];
            cls = fmaf(d, d, cls);
        }
        return dc * dc + LAMBDA_COORD * loc + dn * dn + LAMBDA_CLASS * cls;
    } else {
        const float d4 = o[4] - g[4];
        const float d9 = o[9] - g[9];
        return d4 * d4 + d9 * d9;  // LAMBDA_NOOBJ = 1
    }
}

__device__ __forceinline__ float warp_reduce_sum(float v) {
    #pragma unroll
    for (int off = 16; off > 0; off >>= 1)
        v += __shfl_down_sync(0xFFFFFFFFu, v, off);
    return v;
}

extern __shared__ float dynsmem[];  // [STAGES][2][TILE_FLOATS]

__global__ void __launch_bounds__(TPB)
yolo_pipe3_kernel(const float* __restrict__ pred,
                  const float* __restrict__ gt,
                  long long cells,
                  long long n_batch,
                  float* __restrict__ out)
{
    __shared__ __align__(8) unsigned long long mbar_full[STAGES];
    __shared__ float warp_sums[TPB / 32];

    const int tid = threadIdx.x;
    const long long tiles = cells / TILE_CELLS;

    uint32_t mb[STAGES];
    #pragma unroll
    for (int s = 0; s < STAGES; s++) mb[s] = smem_u32(&mbar_full[s]);

    if (tid == 0) {
        #pragma unroll
        for (int s = 0; s < STAGES; s++) mbar_init(mb[s], 1);
    }
    __syncthreads();

    // number of tiles this block will process
    long long nt = 0;
    if ((long long)blockIdx.x < tiles)
        nt = (tiles - blockIdx.x + gridDim.x - 1) / gridDim.x;

    // prologue: fill all stages
    if (tid == 0) {
        #pragma unroll
        for (int s = 0; s < STAGES; s++)
            if (nt > s)
                issue_tile(pred, gt, dynsmem, s,
                           blockIdx.x + (long long)s * gridDim.x, mb[s]);
    }

    uint32_t phase[STAGES];
    #pragma unroll
    for (int s = 0; s < STAGES; s++) phase[s] = 0;

    float acc = 0.0f;
    int s = 0;

    for (long long j = 0; j < nt; j++) {
        mbar_wait(mb[s], phase[s]);
        phase[s] ^= 1;

        const float* o = dynsmem + (size_t)s * 2 * TILE_FLOATS + tid * CELL_F;
        const float* g = o + TILE_FLOATS;
        acc += cell_loss(o, g);

        __syncthreads();  // all threads done reading stage s

        if (tid == 0 && j + STAGES < nt) {
            const long long tile = blockIdx.x + (j + STAGES) * (long long)gridDim.x;
            issue_tile(pred, gt, dynsmem, s, tile, mb[s]);
        }

        s = (s + 1 == STAGES) ? 0 : s + 1;
    }

    // remainder cells (cells % TILE_CELLS), handled by block 0 via direct loads
    if (blockIdx.x == 0) {
        const long long rem_start = tiles * TILE_CELLS;
        for (long long c = rem_start + tid; c < cells; c += TPB) {
            float oc[CELL_F], gc[CELL_F];
            #pragma unroll
            for (int k = 0; k < CELL_F; k++) {
                oc[k] = __ldg(pred + c * CELL_F + k);
                gc[k] = __ldg(gt   + c * CELL_F + k);
            }
            acc += cell_loss(oc, gc);
        }
    }

    // ---- block reduction ----
    float v = warp_reduce_sum(acc);
    const int wid = tid >> 5;
    const int lid = tid & 31;
    if (lid == 0) warp_sums[wid] = v;
    __syncthreads();

    if (tid == 0) {
        float ssum = 0.0f;
        #pragma unroll
        for (int i = 0; i < TPB / 32; i++) ssum += warp_sums[i];

        atomicAdd(&g_yolo_acc, (double)ssum);
        __threadfence();
        const unsigned int ticket = atomicAdd(&g_yolo_count, 1u);
        if (ticket == gridDim.x - 1) {
            const double total = *((volatile double*)&g_yolo_acc);
            out[0] = (float)(total / (double)n_batch);
            *((volatile double*)&g_yolo_acc) = 0.0;
            *((volatile unsigned int*)&g_yolo_count) = 0u;
        }
    }
}

extern "C" void kernel_launch(void* const* d_in, const int* in_sizes, int n_in,
                              void* d_out, int out_size)
{
    const float* pred = (const float*)d_in[0];   // 'output'
    const float* gt   = (const float*)d_in[1];   // 'ground_truth'
    float* out = (float*)d_out;

    const long long total_elems = (long long)in_sizes[0];       // N*H*W*C
    const long long cells = total_elems / CELL_F;               // N*H*W
    const long long n_batch = total_elems / (6LL * 8 * CELL_F); // N

    const int dyn_bytes = STAGES * 2 * TILE_BYTES;              // 86016

    cudaFuncSetAttribute(yolo_pipe3_kernel,
                         cudaFuncAttributeMaxDynamicSharedMemorySize, dyn_bytes);

    long long tiles = cells / TILE_CELLS;
    int grid = GRID_BLOCKS;
    if (tiles > 0 && tiles < grid) grid = (int)tiles;
    if (grid < 1) grid = 1;

    yolo_pipe3_kernel<<<grid, TPB, dyn_bytes>>>(pred, gt, cells, n_batch, out);
}

// round 8
// speedup vs baseline: 1.0009x; 1.0009x over previous
#include <cuda_runtime.h>
#include <cstdint>

// ---------------------------------------------------------------------------
// YoloLoss on [N=32768, 6, 8, 14] fp32: persistent double-buffered
// cp.async.bulk pipeline with a DEDICATED PRODUCER WARP.
// 444 persistent CTAs x 288 threads (8 consumer warps + 1 producer warp).
// Tile = 256 cells (14336 B per tensor, 28672 B per stage).
// Producer: wait empty[s] -> arm full[s] (expect_tx) -> 2x cp.async.bulk.
// Consumers: wait full[s] -> compute 1 cell/thread -> warp-arrive empty[s].
// No __syncthreads in the steady-state loop; issue is never serialized
// behind block-wide compute completion.
// Last-finishing block finalizes out[0] and resets scratch state.
// ---------------------------------------------------------------------------

#define CELL_F 14
#define CONSUMERS 256
#define TPB 288                              // 256 consumers + 32 producer
#define TILE_CELLS 256
#define TILE_FLOATS (TILE_CELLS * CELL_F)    // 3584 floats
#define TILE_BYTES  (TILE_FLOATS * 4)        // 14336 bytes
#define STAGES 2
#define NWARPS_C (CONSUMERS / 32)            // 8 consumer warps
#define GRID_BLOCKS 444                      // 148 SMs x 3 (smem-limited)

#define LAMBDA_COORD 8.0f
#define LAMBDA_CLASS 0.7f
#define EPS_IOU 1e-10f

__device__ double g_yolo_acc;          // zero-init; reset by last block
__device__ unsigned int g_yolo_count;  // zero-init; reset by last block

__device__ __forceinline__ uint32_t smem_u32(const void* p) {
    return (uint32_t)__cvta_generic_to_shared((void*)p);
}

__device__ __forceinline__ void mbar_init(uint32_t mb, uint32_t count) {
    asm volatile("mbarrier.init.shared::cta.b64 [%0], %1;"
                 :: "r"(mb), "r"(count) : "memory");
}

__device__ __forceinline__ void mbar_arrive(uint32_t mb) {
    asm volatile("mbarrier.arrive.shared::cta.b64 _, [%0];"
                 :: "r"(mb) : "memory");
}

__device__ __forceinline__ void mbar_wait(uint32_t mb, uint32_t phase) {
    uint32_t done = 0;
    while (!done) {
        asm volatile(
            "{\n\t.reg .pred p;\n\t"
            "mbarrier.try_wait.parity.acquire.cta.shared::cta.b64 p, [%1], %2, 0x989680;\n\t"
            "selp.b32 %0, 1, 0, p;\n\t}"
            : "=r"(done) : "r"(mb), "r"(phase) : "memory");
    }
}

__device__ __forceinline__ void issue_tile(const float* __restrict__ pred,
                                           const float* __restrict__ gt,
                                           float* dynsmem, int s,
                                           long long tile, uint32_t mb)
{
    asm volatile("mbarrier.arrive.expect_tx.shared::cta.b64 _, [%0], %1;"
                 :: "r"(mb), "r"(2u * TILE_BYTES) : "memory");
    const char* srcp = (const char*)pred + tile * (long long)TILE_BYTES;
    const char* srcg = (const char*)gt   + tile * (long long)TILE_BYTES;
    uint32_t dso = smem_u32(dynsmem + (size_t)s * 2 * TILE_FLOATS);
    uint32_t dsg = dso + TILE_BYTES;
    asm volatile("cp.async.bulk.shared::cluster.global.mbarrier::complete_tx::bytes "
                 "[%0], [%1], %2, [%3];"
                 :: "r"(dso), "l"(srcp), "r"((uint32_t)TILE_BYTES), "r"(mb) : "memory");
    asm volatile("cp.async.bulk.shared::cluster.global.mbarrier::complete_tx::bytes "
                 "[%0], [%1], %2, [%3];"
                 :: "r"(dsg), "l"(srcg), "r"((uint32_t)TILE_BYTES), "r"(mb) : "memory");
}

__device__ __forceinline__ float cell_loss(const float* __restrict__ o,
                                           const float* __restrict__ g)
{
    const float obj_flag = g[4];  // exactly 0.0f or 1.0f
    if (obj_flag > 0.0f) {
        const float gx = g[0], gy = g[1];
        const float gw = g[2] * g[2], gh = g[3] * g[3];
        const float garea = gw * gh;

        float iou[2];
        #pragma unroll
        for (int b = 0; b < 2; b++) {
            const float x = o[5 * b + 0];
            const float y = o[5 * b + 1];
            const float w = o[5 * b + 2] * o[5 * b + 2];
            const float h = o[5 * b + 3] * o[5 * b + 3];
            const float left  = fmaxf(x - 0.5f * w, gx - 0.5f * gw);
            const float right = fminf(x + 0.5f * w, gx + 0.5f * gw);
            const float top   = fmaxf(y - 0.5f * h, gy - 0.5f * gh);
            const float bot   = fminf(y + 0.5f * h, gy + 0.5f * gh);
            const float inter = fmaxf(right - left, 0.0f) * fmaxf(bot - top, 0.0f);
            const float uni   = w * h + garea - inter;
            iou[b] = inter / (uni + EPS_IOU);
        }
        // jnp.argmax picks FIRST max -> responsible=1 only on strict >
        const int idx = (iou[1] > iou[0]) ? 1 : 0;
        const float max_iou = fmaxf(iou[0], iou[1]);

        const float* pr = o + 5 * idx;
        const float* po = o + 5 * (1 - idx);
        const float* gr = g + 5 * idx;
        const float* go = g + 5 * (1 - idx);

        float loc = 0.0f;
        #pragma unroll
        for (int c = 0; c < 4; c++) {
            const float d = pr[c] - gr[c];
            loc = fmaf(d, d, loc);
        }
        const float dc = pr[4] - max_iou;
        const float dn = po[4] - go[4];

        float cls = 0.0f;
        #pragma unroll
        for (int c = 10; c < 14; c++) {
            const float d = o[c] - g[c];
            cls = fmaf(d, d, cls);
        }
        return dc * dc + LAMBDA_COORD * loc + dn * dn + LAMBDA_CLASS * cls;
    } else {
        const float d4 = o[4] - g[4];
        const float d9 = o[9] - g[9];
        return d4 * d4 + d9 * d9;  // LAMBDA_NOOBJ = 1
    }
}

__device__ __forceinline__ float warp_reduce_sum(float v) {
    #pragma unroll
    for (int off = 16; off > 0; off >>= 1)
        v += __shfl_down_sync(0xFFFFFFFFu, v, off);
    return v;
}

extern __shared__ float dynsmem[];  // [STAGES][2][TILE_FLOATS]

__global__ void __launch_bounds__(TPB)
yolo_ws_kernel(const float* __restrict__ pred,
               const float* __restrict__ gt,
               long long cells,
               long long n_batch,
               float* __restrict__ out)
{
    __shared__ __align__(8) unsigned long long mbar_full[STAGES];
    __shared__ __align__(8) unsigned long long mbar_empty[STAGES];
    __shared__ float warp_sums[NWARPS_C];

    const int tid = threadIdx.x;
    const int wid = tid >> 5;
    const int lid = tid & 31;
    const long long tiles = cells / TILE_CELLS;

    uint32_t mbf[STAGES], mbe[STAGES];
    #pragma unroll
    for (int s = 0; s < STAGES; s++) {
        mbf[s] = smem_u32(&mbar_full[s]);
        mbe[s] = smem_u32(&mbar_empty[s]);
    }

    if (tid == 0) {
        #pragma unroll
        for (int s = 0; s < STAGES; s++) {
            mbar_init(mbf[s], 1);         // one expect_tx arm per tile
            mbar_init(mbe[s], NWARPS_C);  // 8 consumer-warp arrivals
        }
    }
    __syncthreads();

    // number of tiles this block will process
    long long nt = 0;
    if ((long long)blockIdx.x < tiles)
        nt = (tiles - blockIdx.x + gridDim.x - 1) / gridDim.x;

    float acc = 0.0f;

    if (wid == NWARPS_C) {
        // -------- producer warp: lane 0 issues, bounded by empty barriers ----
        if (lid == 0) {
            uint32_t pe[STAGES];
            #pragma unroll
            for (int s = 0; s < STAGES; s++) pe[s] = 1;  // first waits pass
            int s = 0;
            for (long long j = 0; j < nt; j++) {
                mbar_wait(mbe[s], pe[s]);
                pe[s] ^= 1;
                const long long tile = blockIdx.x + j * (long long)gridDim.x;
                issue_tile(pred, gt, dynsmem, s, tile, mbf[s]);
                s = (s + 1 == STAGES) ? 0 : s + 1;
            }
        }
    } else {
        // -------- consumer warps ----
        uint32_t pf[STAGES];
        #pragma unroll
        for (int s = 0; s < STAGES; s++) pf[s] = 0;
        int s = 0;
        for (long long j = 0; j < nt; j++) {
            mbar_wait(mbf[s], pf[s]);
            pf[s] ^= 1;

            const float* o = dynsmem + (size_t)s * 2 * TILE_FLOATS + tid * CELL_F;
            const float* g = o + TILE_FLOATS;
            acc += cell_loss(o, g);

            __syncwarp();
            if (lid == 0) mbar_arrive(mbe[s]);

            s = (s + 1 == STAGES) ? 0 : s + 1;
        }

        // remainder cells (cells % TILE_CELLS), handled by block 0
        if (blockIdx.x == 0) {
            const long long rem_start = tiles * TILE_CELLS;
            for (long long c = rem_start + tid; c < cells; c += CONSUMERS) {
                float oc[CELL_F], gc[CELL_F];
                #pragma unroll
                for (int k = 0; k < CELL_F; k++) {
                    oc[k] = __ldg(pred + c * CELL_F + k);
                    gc[k] = __ldg(gt   + c * CELL_F + k);
                }
                acc += cell_loss(oc, gc);
            }
        }
    }

    // ---- block reduction (producer warp contributes 0) ----
    float v = warp_reduce_sum(acc);
    if (wid < NWARPS_C && lid == 0) warp_sums[wid] = v;
    __syncthreads();

    if (tid == 0) {
        float ssum = 0.0f;
        #pragma unroll
        for (int i = 0; i < NWARPS_C; i++) ssum += warp_sums[i];

        atomicAdd(&g_yolo_acc, (double)ssum);
        __threadfence();
        const unsigned int ticket = atomicAdd(&g_yolo_count, 1u);
        if (ticket == gridDim.x - 1) {
            const double total = *((volatile double*)&g_yolo_acc);
            out[0] = (float)(total / (double)n_batch);
            *((volatile double*)&g_yolo_acc) = 0.0;
            *((volatile unsigned int*)&g_yolo_count) = 0u;
        }
    }
}

extern "C" void kernel_launch(void* const* d_in, const int* in_sizes, int n_in,
                              void* d_out, int out_size)
{
    const float* pred = (const float*)d_in[0];   // 'output'
    const float* gt   = (const float*)d_in[1];   // 'ground_truth'
    float* out = (float*)d_out;

    const long long total_elems = (long long)in_sizes[0];       // N*H*W*C
    const long long cells = total_elems / CELL_F;               // N*H*W
    const long long n_batch = total_elems / (6LL * 8 * CELL_F); // N

    const int dyn_bytes = STAGES * 2 * TILE_BYTES;              // 57344

    cudaFuncSetAttribute(yolo_ws_kernel,
                         cudaFuncAttributeMaxDynamicSharedMemorySize, dyn_bytes);

    long long tiles = cells / TILE_CELLS;
    int grid = GRID_BLOCKS;
    if (tiles > 0 && tiles < grid) grid = (int)tiles;
    if (grid < 1) grid = 1;

    yolo_ws_kernel<<<grid, TPB, dyn_bytes>>>(pred, gt, cells, n_batch, out);
}